// round 3
// baseline (speedup 1.0000x reference)
#include <cuda_runtime.h>
#include <cuda_bf16.h>

// Problem constants
#define BB 4
#define SS 1024
#define DD 4096
#define HH 32
#define HD 128
#define BS (BB*SS)        // 4096 rows
#define NEG_INF (-1e30f)

// ---------------------------------------------------------------------------
// Scratch (allocation-free rule: __device__ globals)
// ---------------------------------------------------------------------------
__device__ float g_q[BS * DD];
__device__ float g_k[BS * DD];
__device__ float g_v[BS * DD];
__device__ float g_attn[BS * DD];

// ---------------------------------------------------------------------------
// SGEMM:  C[M,N] = A[M,K] * W[N,K]^T   (M=N=K=4096, both K-contiguous)
// 128x128 block tile, BK=8, 256 threads, 8x8 per-thread micro-tile.
// Optional fused RoPE on the epilogue (for Q/K projections).
// ---------------------------------------------------------------------------
template<bool ROPE>
__global__ __launch_bounds__(256, 2)
void gemm_nt_kernel(const float* __restrict__ A,
                    const float* __restrict__ W,
                    float* __restrict__ C,
                    const float* __restrict__ cosb,
                    const float* __restrict__ sinb)
{
    __shared__ float As[8][129];
    __shared__ float Bs[8][129];

    const int tid = threadIdx.x;
    const int tx  = tid & 15;        // N direction
    const int ty  = tid >> 4;        // M direction
    const int m0  = blockIdx.y * 128;
    const int n0  = blockIdx.x * 128;

    // load mapping: each thread loads one float4 of A and one of W per k-tile
    const int lr = tid >> 1;         // 0..127 (row within tile)
    const int lk = (tid & 1) * 4;    // 0 or 4 (k offset)

    const float* Ap = A + (size_t)(m0 + lr) * DD + lk;
    const float* Wp = W + (size_t)(n0 + lr) * DD + lk;

    float acc[8][8];
    #pragma unroll
    for (int i = 0; i < 8; i++)
        #pragma unroll
        for (int j = 0; j < 8; j++) acc[i][j] = 0.f;

    for (int k0 = 0; k0 < DD; k0 += 8) {
        float4 va = *(const float4*)(Ap + k0);
        float4 vb = *(const float4*)(Wp + k0);
        __syncthreads();               // previous tile consumed
        As[lk + 0][lr] = va.x; As[lk + 1][lr] = va.y;
        As[lk + 2][lr] = va.z; As[lk + 3][lr] = va.w;
        Bs[lk + 0][lr] = vb.x; Bs[lk + 1][lr] = vb.y;
        Bs[lk + 2][lr] = vb.z; Bs[lk + 3][lr] = vb.w;
        __syncthreads();

        #pragma unroll
        for (int kk = 0; kk < 8; kk++) {
            float a[8], b[8];
            #pragma unroll
            for (int i = 0; i < 8; i++) a[i] = As[kk][ty * 8 + i];
            #pragma unroll
            for (int j = 0; j < 8; j++) b[j] = Bs[kk][tx * 8 + j];
            #pragma unroll
            for (int i = 0; i < 8; i++)
                #pragma unroll
                for (int j = 0; j < 8; j++)
                    acc[i][j] += a[i] * b[j];
        }
    }

    // epilogue (+ optional RoPE): row m = b*S + s  ->  s = m & (S-1)
    #pragma unroll
    for (int i = 0; i < 8; i++) {
        const int m = m0 + ty * 8 + i;
        const int ncol = n0 + tx * 8;
        if (ROPE) {
            const int sp = m & (SS - 1);
            #pragma unroll
            for (int j = 0; j < 8; j += 2) {
                const int pi = ((ncol + j) & (HD - 1)) >> 1;   // pair idx in head
                const float c = cosb[sp * (HD / 2) + pi];
                const float s = sinb[sp * (HD / 2) + pi];
                const float re = acc[i][j];
                const float im = acc[i][j + 1];
                acc[i][j]     = re * c - im * s;
                acc[i][j + 1] = re * s + im * c;
            }
        }
        float* Crow = C + (size_t)m * DD + ncol;
        *(float4*)(Crow)     = make_float4(acc[i][0], acc[i][1], acc[i][2], acc[i][3]);
        *(float4*)(Crow + 4) = make_float4(acc[i][4], acc[i][5], acc[i][6], acc[i][7]);
    }
}

// ---------------------------------------------------------------------------
// Flash attention (causal), fp32.
// grid = (S/64, B*H). CTA: 64 q-rows, loop over 64-row KV tiles (0..qb).
// 256 threads. Scores: 4x4/thread; O accumulators: 4 rows x 8 cols/thread.
// ---------------------------------------------------------------------------
#define QT_STRIDE 65
#define V_STRIDE 132
#define SC_STRIDE 65

__global__ __launch_bounds__(256)
void attn_kernel(const float* __restrict__ Q,
                 const float* __restrict__ K,
                 const float* __restrict__ V,
                 float* __restrict__ O)
{
    extern __shared__ float sm[];
    float* qT   = sm;                         // [128][65]  (transposed)
    float* kT   = qT + 128 * QT_STRIDE;       // [128][65]  (transposed)
    float* vs   = kT + 128 * QT_STRIDE;       // [64][132]
    float* sc   = vs + 64 * V_STRIDE;         // [64][65]   scores/probs
    float* m_s  = sc + 64 * SC_STRIDE;        // [64]
    float* l_s  = m_s + 64;                   // [64]
    float* al_s = l_s + 64;                   // [64]

    const int tid = threadIdx.x;
    const int qb  = blockIdx.x;
    const int bh  = blockIdx.y;
    const int b   = bh >> 5;
    const int h   = bh & 31;
    const size_t headoff = (size_t)h * HD;
    const int q0 = qb * 64;

    // load Q tile transposed (coalesced global, conflict-free STS)
    for (int t = tid; t < 64 * 128; t += 256) {
        const int r = t >> 7, d = t & 127;
        qT[d * QT_STRIDE + r] =
            Q[(size_t)(b * SS + q0 + r) * DD + headoff + d];
    }
    if (tid < 64) { m_s[tid] = NEG_INF; l_s[tid] = 0.f; }

    const int tx = tid & 15, ty = tid >> 4;
    const int r0  = ty * 4;      // rows (shared by score + O phases)
    const int c0s = tx * 4;      // score cols

    float o[4][8];               // O col = tx + 16*cc
    #pragma unroll
    for (int i = 0; i < 4; i++)
        #pragma unroll
        for (int cc = 0; cc < 8; cc++) o[i][cc] = 0.f;

    const float scale = 0.088388347648318447f;  // 1/sqrt(128)

    for (int kv = 0; kv <= qb; kv++) {
        const int k0r = kv * 64;
        __syncthreads();   // prior PV done (and Q load on first iter)

        for (int t = tid; t < 64 * 128; t += 256) {
            const int r = t >> 7, d = t & 127;
            const size_t g = (size_t)(b * SS + k0r + r) * DD + headoff + d;
            kT[d * QT_STRIDE + r] = K[g];
            vs[r * V_STRIDE + d]  = V[g];
        }
        __syncthreads();

        // ---- scores: S = Qtile * Ktile^T (64x64), 4x4 per thread
        float s4[4][4];
        #pragma unroll
        for (int i = 0; i < 4; i++)
            #pragma unroll
            for (int j = 0; j < 4; j++) s4[i][j] = 0.f;

        #pragma unroll 4
        for (int kk = 0; kk < 128; kk++) {
            float a[4], bb[4];
            #pragma unroll
            for (int i = 0; i < 4; i++) a[i]  = qT[kk * QT_STRIDE + r0 + i];
            #pragma unroll
            for (int j = 0; j < 4; j++) bb[j] = kT[kk * QT_STRIDE + c0s + j];
            #pragma unroll
            for (int i = 0; i < 4; i++)
                #pragma unroll
                for (int j = 0; j < 4; j++)
                    s4[i][j] += a[i] * bb[j];
        }
        #pragma unroll
        for (int i = 0; i < 4; i++)
            #pragma unroll
            for (int j = 0; j < 4; j++)
                sc[(r0 + i) * SC_STRIDE + c0s + j] = s4[i][j];
        __syncthreads();

        // ---- online softmax: warp w handles rows w*8..w*8+7
        {
            const int wp = tid >> 5, ln = tid & 31;
            const bool diag = (kv == qb);
            for (int rr = 0; rr < 8; rr++) {
                const int r = wp * 8 + rr;
                const int qidx = q0 + r;
                float v0 = sc[r * SC_STRIDE + ln] * scale;
                float v1 = sc[r * SC_STRIDE + 32 + ln] * scale;
                if (diag) {
                    if (k0r + ln > qidx)      v0 = NEG_INF;
                    if (k0r + 32 + ln > qidx) v1 = NEG_INF;
                }
                float mx = fmaxf(v0, v1);
                #pragma unroll
                for (int off = 16; off; off >>= 1)
                    mx = fmaxf(mx, __shfl_xor_sync(0xffffffffu, mx, off));
                const float mold = m_s[r];
                const float mnew = fmaxf(mold, mx);
                const float p0 = __expf(v0 - mnew);
                const float p1 = __expf(v1 - mnew);
                float sum = p0 + p1;
                #pragma unroll
                for (int off = 16; off; off >>= 1)
                    sum += __shfl_xor_sync(0xffffffffu, sum, off);
                sc[r * SC_STRIDE + ln]      = p0;
                sc[r * SC_STRIDE + 32 + ln] = p1;
                if (ln == 0) {
                    const float alpha = __expf(mold - mnew);
                    al_s[r] = alpha;
                    m_s[r]  = mnew;
                    l_s[r]  = l_s[r] * alpha + sum;
                }
            }
        }
        __syncthreads();

        // ---- PV: O = O*alpha + P(64x64) * V(64x128)
        float a4[4];
        #pragma unroll
        for (int i = 0; i < 4; i++) a4[i] = al_s[r0 + i];
        #pragma unroll
        for (int i = 0; i < 4; i++)
            #pragma unroll
            for (int cc = 0; cc < 8; cc++) o[i][cc] *= a4[i];

        #pragma unroll 2
        for (int j = 0; j < 64; j++) {
            float p[4], vv[8];
            #pragma unroll
            for (int i = 0; i < 4; i++) p[i] = sc[(r0 + i) * SC_STRIDE + j];
            #pragma unroll
            for (int cc = 0; cc < 8; cc++) vv[cc] = vs[j * V_STRIDE + tx + 16 * cc];
            #pragma unroll
            for (int i = 0; i < 4; i++)
                #pragma unroll
                for (int cc = 0; cc < 8; cc++)
                    o[i][cc] += p[i] * vv[cc];
        }
    }

    // epilogue: normalize and store (B,S,H,HD) == (B*S, D) row-major
    #pragma unroll
    for (int i = 0; i < 4; i++) {
        const float inv = 1.f / l_s[r0 + i];
        const size_t base = (size_t)(b * SS + q0 + r0 + i) * DD + headoff;
        #pragma unroll
        for (int cc = 0; cc < 8; cc++)
            O[base + tx + 16 * cc] = o[i][cc] * inv;
    }
}

// ---------------------------------------------------------------------------
// kernel_launch
// inputs: 0:x 1:wq 2:wk 3:wv 4:wo 5:freqs_cos 6:freqs_sin 7:mask(unused)
// ---------------------------------------------------------------------------
extern "C" void kernel_launch(void* const* d_in, const int* in_sizes, int n_in,
                              void* d_out, int out_size)
{
    const float* x    = (const float*)d_in[0];
    const float* wq   = (const float*)d_in[1];
    const float* wk   = (const float*)d_in[2];
    const float* wv   = (const float*)d_in[3];
    const float* wo   = (const float*)d_in[4];
    const float* cosb = (const float*)d_in[5];
    const float* sinb = (const float*)d_in[6];
    float* out = (float*)d_out;

    float *pq, *pk, *pv, *pa;
    cudaGetSymbolAddress((void**)&pq, g_q);
    cudaGetSymbolAddress((void**)&pk, g_k);
    cudaGetSymbolAddress((void**)&pv, g_v);
    cudaGetSymbolAddress((void**)&pa, g_attn);

    const int attn_smem = (128 * QT_STRIDE * 2 + 64 * V_STRIDE +
                           64 * SC_STRIDE + 3 * 64) * (int)sizeof(float);
    cudaFuncSetAttribute(attn_kernel,
                         cudaFuncAttributeMaxDynamicSharedMemorySize, attn_smem);

    dim3 ggrid(DD / 128, BS / 128);   // 32 x 32
    dim3 gblk(256);

    gemm_nt_kernel<true ><<<ggrid, gblk>>>(x, wq, pq, cosb, sinb);
    gemm_nt_kernel<true ><<<ggrid, gblk>>>(x, wk, pk, cosb, sinb);
    gemm_nt_kernel<false><<<ggrid, gblk>>>(x, wv, pv, nullptr, nullptr);

    dim3 agrid(SS / 64, BB * HH);     // 16 x 128
    attn_kernel<<<agrid, dim3(256), attn_smem>>>(pq, pk, pv, pa);

    gemm_nt_kernel<false><<<ggrid, gblk>>>(pa, wo, out, nullptr, nullptr);
}